// round 1
// baseline (speedup 1.0000x reference)
#include <cuda_runtime.h>
#include <math.h>

#define NPTS 1024
#define NF   32     // frequency pairs (sin+cos => 64 features)
#define NH   16     // heads

// Scratch for normalized direction vectors (max B=2)
__device__ float g_vn[2 * NPTS * 3];

__global__ void normalize_kernel(const float* __restrict__ vec, int total) {
    int idx = blockIdx.x * blockDim.x + threadIdx.x;
    if (idx >= total) return;
    float x = vec[idx * 3 + 0];
    float y = vec[idx * 3 + 1];
    float z = vec[idx * 3 + 2];
    float n = sqrtf(x * x + y * y + z * z);
    g_vn[idx * 3 + 0] = x / n;
    g_vn[idx * 3 + 1] = y / n;
    g_vn[idx * 3 + 2] = z / n;
}

// ---- packed f32x2 helpers (Blackwell FFMA2 path) ----
__device__ __forceinline__ unsigned long long pack_dup(float x) {
    unsigned long long r;
    asm("mov.b64 %0, {%1, %1};" : "=l"(r) : "f"(x));
    return r;
}
__device__ __forceinline__ unsigned long long pack2(float lo, float hi) {
    unsigned long long r;
    asm("mov.b64 %0, {%1, %2};" : "=l"(r) : "f"(lo), "f"(hi));
    return r;
}
__device__ __forceinline__ void fma2(unsigned long long& d,
                                     unsigned long long a,
                                     unsigned long long b) {
    asm("fma.rn.f32x2 %0, %1, %2, %0;" : "+l"(d) : "l"(a), "l"(b));
}
__device__ __forceinline__ float2 unpack2(unsigned long long v) {
    float lo, hi;
    asm("mov.b64 {%0, %1}, %2;" : "=f"(lo), "=f"(hi) : "l"(v));
    return make_float2(lo, hi);
}

// One thread = one (i, j) pair. Block = 256 consecutive j for one (b, i).
__global__ __launch_bounds__(256)
void relbias_kernel(const float* __restrict__ W,   // [64, 16]
                    const float* __restrict__ bias, // [16]
                    float* __restrict__ out) {
    __shared__ __align__(16) float sW[2 * NF * NH]; // rows 0..31 sin, 32..63 cos
    __shared__ float sB[NH];

    int tid = threadIdx.x;
    for (int idx = tid; idx < 2 * NF * NH; idx += 256) sW[idx] = W[idx];
    if (tid < NH) sB[tid] = bias[tid];
    __syncthreads();

    int b = blockIdx.z;
    int i = blockIdx.y;
    int j = blockIdx.x * 256 + tid;

    const float* vi = &g_vn[(b * NPTS + i) * 3];
    const float* vj = &g_vn[(b * NPTS + j) * 3];
    float dx = vi[0] - vj[0];
    float dy = vi[1] - vj[1];
    float dz = vi[2] - vj[2];
    float dot = 1.0f - 0.5f * ((dx * dx + dy * dy) + dz * dz);
    dot = fminf(fmaxf(dot, -1.0f), 1.0f);
    float angle = acosf(dot) * 200.0f;          // / 0.005
    float t = angle * (10.0f / 31.0f);          // base phase step

    // range-reduce t mod 2*pi in double (cheap: once per pair), then fast sin/cos
    double td = (double)t;
    double q = rint(td * 0.15915494309189535);  // 1/(2*pi)
    float tr = (float)(td - q * 6.283185307179586);
    float s1 = __sinf(tr);
    float c1 = __cosf(tr);

    // accumulators: 8 packed pairs = 16 heads, init with bias
    unsigned long long acc[8];
#pragma unroll
    for (int p = 0; p < 8; ++p) acc[p] = pack2(sB[2 * p], sB[2 * p + 1]);

    const ulonglong2* sWs2 = (const ulonglong2*)sW;             // 4 u2 per row
    const ulonglong2* sWc2 = (const ulonglong2*)(sW + NF * NH);

    float s = 0.0f, c = 1.0f;                   // sin(0*t), cos(0*t)
#pragma unroll
    for (int k = 0; k < NF; ++k) {
        ulonglong2 a0 = sWs2[4 * k + 0];
        ulonglong2 a1 = sWs2[4 * k + 1];
        ulonglong2 a2 = sWs2[4 * k + 2];
        ulonglong2 a3 = sWs2[4 * k + 3];
        ulonglong2 b0 = sWc2[4 * k + 0];
        ulonglong2 b1 = sWc2[4 * k + 1];
        ulonglong2 b2 = sWc2[4 * k + 2];
        ulonglong2 b3 = sWc2[4 * k + 3];
        unsigned long long sp = pack_dup(s);
        unsigned long long cp = pack_dup(c);
        fma2(acc[0], sp, a0.x); fma2(acc[1], sp, a0.y);
        fma2(acc[2], sp, a1.x); fma2(acc[3], sp, a1.y);
        fma2(acc[4], sp, a2.x); fma2(acc[5], sp, a2.y);
        fma2(acc[6], sp, a3.x); fma2(acc[7], sp, a3.y);
        fma2(acc[0], cp, b0.x); fma2(acc[1], cp, b0.y);
        fma2(acc[2], cp, b1.x); fma2(acc[3], cp, b1.y);
        fma2(acc[4], cp, b2.x); fma2(acc[5], cp, b2.y);
        fma2(acc[6], cp, b3.x); fma2(acc[7], cp, b3.y);
        // rotate: (s, c) -> (s*c1 + c*s1, c*c1 - s*s1)
        float ns = fmaf(s, c1, c * s1);
        float nc = fmaf(c, c1, -(s * s1));
        s = ns;
        c = nc;
    }

    // write 16 floats for this pair
    long long pidx = ((long long)(b * NPTS + i) * NPTS + j);
    float4* o4 = (float4*)out + pidx * 4;
#pragma unroll
    for (int p = 0; p < 4; ++p) {
        float2 lo = unpack2(acc[2 * p]);
        float2 hi = unpack2(acc[2 * p + 1]);
        o4[p] = make_float4(lo.x, lo.y, hi.x, hi.y);
    }
}

extern "C" void kernel_launch(void* const* d_in, const int* in_sizes, int n_in,
                              void* d_out, int out_size) {
    const float* vec_map = (const float*)d_in[0];
    const float* kernelW = (const float*)d_in[1];
    const float* bias    = (const float*)d_in[2];
    float* out = (float*)d_out;

    int total_vecs = in_sizes[0] / 3;       // B * N
    int B = total_vecs / NPTS;

    normalize_kernel<<<(total_vecs + 255) / 256, 256>>>(vec_map, total_vecs);

    dim3 grid(NPTS / 256, NPTS, B);
    relbias_kernel<<<grid, 256>>>(kernelW, bias, out);
}

// round 2
// speedup vs baseline: 1.2254x; 1.2254x over previous
#include <cuda_runtime.h>
#include <math.h>

#define NPTS 1024
#define NF   32     // frequency pairs (sin+cos => 64 features)
#define NH   16     // heads
#define TJ   4      // j-values per thread

// Scratch for normalized direction vectors (max B=2)
__device__ float g_vn[2 * NPTS * 3];

__global__ void normalize_kernel(const float* __restrict__ vec, int total) {
    int idx = blockIdx.x * blockDim.x + threadIdx.x;
    if (idx >= total) return;
    float x = vec[idx * 3 + 0];
    float y = vec[idx * 3 + 1];
    float z = vec[idx * 3 + 2];
    float n = sqrtf(x * x + y * y + z * z);
    g_vn[idx * 3 + 0] = x / n;
    g_vn[idx * 3 + 1] = y / n;
    g_vn[idx * 3 + 2] = z / n;
}

// ---- packed f32x2 helpers (Blackwell FFMA2 path) ----
__device__ __forceinline__ unsigned long long pack_dup(float x) {
    unsigned long long r;
    asm("mov.b64 %0, {%1, %1};" : "=l"(r) : "f"(x));
    return r;
}
__device__ __forceinline__ unsigned long long pack2(float lo, float hi) {
    unsigned long long r;
    asm("mov.b64 %0, {%1, %2};" : "=l"(r) : "f"(lo), "f"(hi));
    return r;
}
__device__ __forceinline__ void fma2(unsigned long long& d,
                                     unsigned long long a,
                                     unsigned long long b) {
    asm("fma.rn.f32x2 %0, %1, %2, %0;" : "+l"(d) : "l"(a), "l"(b));
}
__device__ __forceinline__ float2 unpack2(unsigned long long v) {
    float lo, hi;
    asm("mov.b64 {%0, %1}, %2;" : "=f"(lo), "=f"(hi) : "l"(v));
    return make_float2(lo, hi);
}

// One thread = TJ (i, j) pairs. Block (256 threads) covers a full row i:
// thread tid handles j = tid, tid+256, tid+512, tid+768.
__global__ __launch_bounds__(256)
void relbias_kernel(const float* __restrict__ W,    // [64, 16]
                    const float* __restrict__ bias, // [16]
                    float* __restrict__ out) {
    __shared__ __align__(16) float sW[2 * NF * NH]; // rows 0..31 sin, 32..63 cos
    __shared__ float sB[NH];

    int tid = threadIdx.x;
    for (int idx = tid; idx < 2 * NF * NH; idx += 256) sW[idx] = W[idx];
    if (tid < NH) sB[tid] = bias[tid];
    __syncthreads();

    int i = blockIdx.x;
    int b = blockIdx.y;

    const float* vi = &g_vn[(b * NPTS + i) * 3];
    float vix = vi[0], viy = vi[1], viz = vi[2];

    float s[TJ], c[TJ], s1[TJ], c1[TJ];
#pragma unroll
    for (int p = 0; p < TJ; ++p) {
        int j = tid + 256 * p;
        const float* vj = &g_vn[(b * NPTS + j) * 3];
        float dx = vix - vj[0];
        float dy = viy - vj[1];
        float dz = viz - vj[2];
        float dot = 1.0f - 0.5f * ((dx * dx + dy * dy) + dz * dz);
        dot = fminf(fmaxf(dot, -1.0f), 1.0f);
        float angle = acosf(dot) * 200.0f;       // / 0.005
        float t = angle * (10.0f / 31.0f);       // base phase step

        // range-reduce t mod 2*pi in double (once per pair), then fast sin/cos
        double td = (double)t;
        double q = rint(td * 0.15915494309189535);  // 1/(2*pi)
        float tr = (float)(td - q * 6.283185307179586);
        s1[p] = __sinf(tr);
        c1[p] = __cosf(tr);
        s[p] = 0.0f;   // sin(0*t)
        c[p] = 1.0f;   // cos(0*t)
    }

    // accumulators: TJ pairs x 8 packed f32x2 = 16 heads each, init with bias
    unsigned long long acc[TJ][8];
    {
        unsigned long long b0 = pack2(sB[0],  sB[1]);
        unsigned long long b1 = pack2(sB[2],  sB[3]);
        unsigned long long b2 = pack2(sB[4],  sB[5]);
        unsigned long long b3 = pack2(sB[6],  sB[7]);
        unsigned long long b4 = pack2(sB[8],  sB[9]);
        unsigned long long b5 = pack2(sB[10], sB[11]);
        unsigned long long b6 = pack2(sB[12], sB[13]);
        unsigned long long b7 = pack2(sB[14], sB[15]);
#pragma unroll
        for (int p = 0; p < TJ; ++p) {
            acc[p][0] = b0; acc[p][1] = b1; acc[p][2] = b2; acc[p][3] = b3;
            acc[p][4] = b4; acc[p][5] = b5; acc[p][6] = b6; acc[p][7] = b7;
        }
    }

    const ulonglong2* sWs2 = (const ulonglong2*)sW;             // 4 u2 per row
    const ulonglong2* sWc2 = (const ulonglong2*)(sW + NF * NH);

#pragma unroll 2
    for (int k = 0; k < NF; ++k) {
        // hoist the 8 weight vectors for this frequency; reuse across TJ pairs
        ulonglong2 a0 = sWs2[4 * k + 0];
        ulonglong2 a1 = sWs2[4 * k + 1];
        ulonglong2 a2 = sWs2[4 * k + 2];
        ulonglong2 a3 = sWs2[4 * k + 3];
        ulonglong2 w0 = sWc2[4 * k + 0];
        ulonglong2 w1 = sWc2[4 * k + 1];
        ulonglong2 w2 = sWc2[4 * k + 2];
        ulonglong2 w3 = sWc2[4 * k + 3];
#pragma unroll
        for (int p = 0; p < TJ; ++p) {
            unsigned long long sp = pack_dup(s[p]);
            unsigned long long cp = pack_dup(c[p]);
            fma2(acc[p][0], sp, a0.x); fma2(acc[p][1], sp, a0.y);
            fma2(acc[p][2], sp, a1.x); fma2(acc[p][3], sp, a1.y);
            fma2(acc[p][4], sp, a2.x); fma2(acc[p][5], sp, a2.y);
            fma2(acc[p][6], sp, a3.x); fma2(acc[p][7], sp, a3.y);
            fma2(acc[p][0], cp, w0.x); fma2(acc[p][1], cp, w0.y);
            fma2(acc[p][2], cp, w1.x); fma2(acc[p][3], cp, w1.y);
            fma2(acc[p][4], cp, w2.x); fma2(acc[p][5], cp, w2.y);
            fma2(acc[p][6], cp, w3.x); fma2(acc[p][7], cp, w3.y);
            // rotate: (s, c) -> (s*c1 + c*s1, c*c1 - s*s1)
            float ns = fmaf(s[p], c1[p], c[p] * s1[p]);
            float nc = fmaf(c[p], c1[p], -(s[p] * s1[p]));
            s[p] = ns;
            c[p] = nc;
        }
    }

    // write 16 floats per pair
    long long rowbase = ((long long)(b * NPTS + i) * NPTS);
#pragma unroll
    for (int p = 0; p < TJ; ++p) {
        int j = tid + 256 * p;
        float4* o4 = (float4*)out + (rowbase + j) * 4;
#pragma unroll
        for (int q = 0; q < 4; ++q) {
            float2 lo = unpack2(acc[p][2 * q]);
            float2 hi = unpack2(acc[p][2 * q + 1]);
            o4[q] = make_float4(lo.x, lo.y, hi.x, hi.y);
        }
    }
}

extern "C" void kernel_launch(void* const* d_in, const int* in_sizes, int n_in,
                              void* d_out, int out_size) {
    const float* vec_map = (const float*)d_in[0];
    const float* kernelW = (const float*)d_in[1];
    const float* bias    = (const float*)d_in[2];
    float* out = (float*)d_out;

    int total_vecs = in_sizes[0] / 3;       // B * N
    int B = total_vecs / NPTS;

    normalize_kernel<<<(total_vecs + 255) / 256, 256>>>(vec_map, total_vecs);

    dim3 grid(NPTS, B);
    relbias_kernel<<<grid, 256>>>(kernelW, bias, out);
}

// round 3
// speedup vs baseline: 1.6742x; 1.3662x over previous
#include <cuda_runtime.h>
#include <math.h>

#define NPTS 1024
#define NF   32     // frequency pairs (sin+cos => 64 features)
#define NH   16     // heads

// Scratch for normalized direction vectors (max B=2)
__device__ float g_vn[2 * NPTS * 3];

__global__ void normalize_kernel(const float* __restrict__ vec, int total) {
    int idx = blockIdx.x * blockDim.x + threadIdx.x;
    if (idx >= total) return;
    float x = vec[idx * 3 + 0];
    float y = vec[idx * 3 + 1];
    float z = vec[idx * 3 + 2];
    float n = sqrtf(x * x + y * y + z * z);
    g_vn[idx * 3 + 0] = x / n;
    g_vn[idx * 3 + 1] = y / n;
    g_vn[idx * 3 + 2] = z / n;
}

// Diagonal: angle = 0 -> pos = [0..0, 1..1] -> out = sum_k Wc[k,:] + bias
__global__ void diag_kernel(const float* __restrict__ W,
                            const float* __restrict__ bias,
                            float* __restrict__ out, int total) {
    int idx = blockIdx.x * blockDim.x + threadIdx.x;   // b*NPTS + i
    if (idx >= total) return;
    float acc[NH];
#pragma unroll
    for (int h = 0; h < NH; ++h) acc[h] = bias[h];
    for (int k = 0; k < NF; ++k) {
#pragma unroll
        for (int h = 0; h < NH; ++h) acc[h] += W[(NF + k) * NH + h];
    }
    long long o = ((long long)idx * NPTS + (idx & (NPTS - 1))) * NH;
    float4* o4 = (float4*)(out + o);
#pragma unroll
    for (int q = 0; q < 4; ++q)
        o4[q] = make_float4(acc[4 * q], acc[4 * q + 1], acc[4 * q + 2], acc[4 * q + 3]);
}

// ---- packed f32x2 helpers (Blackwell FFMA2 path) ----
__device__ __forceinline__ unsigned long long pack_dup(float x) {
    unsigned long long r;
    asm("mov.b64 %0, {%1, %1};" : "=l"(r) : "f"(x));
    return r;
}
__device__ __forceinline__ unsigned long long pack2(float lo, float hi) {
    unsigned long long r;
    asm("mov.b64 %0, {%1, %2};" : "=l"(r) : "f"(lo), "f"(hi));
    return r;
}
__device__ __forceinline__ void fma2(unsigned long long& d,
                                     unsigned long long a,
                                     unsigned long long b) {
    asm("fma.rn.f32x2 %0, %1, %2, %0;" : "+l"(d) : "l"(a), "l"(b));
}
__device__ __forceinline__ float2 unpack2(unsigned long long v) {
    float lo, hi;
    asm("mov.b64 {%0, %1}, %2;" : "=f"(lo), "=f"(hi) : "l"(v));
    return make_float2(lo, hi);
}

// Symmetry-halved kernel. Block handles rows i and i+512; thread tid handles
// 4 pairs: (row r, offset d) for r in {i, i+512}, d in {tid+1, tid+257}.
// j = (row + d) mod 1024. Covers every off-diagonal unordered pair once
// (distance-512 twice, identical values). Writes out[i,j] and out[j,i].
__global__ __launch_bounds__(256, 2)
void relbias_kernel(const float* __restrict__ W,    // [64, 16]
                    const float* __restrict__ bias, // [16]
                    float* __restrict__ out) {
    __shared__ __align__(16) float sW[2 * NF * NH]; // rows 0..31 sin, 32..63 cos
    __shared__ float sB[NH];

    int tid = threadIdx.x;
    for (int idx = tid; idx < 2 * NF * NH; idx += 256) sW[idx] = W[idx];
    if (tid < NH) sB[tid] = bias[tid];
    __syncthreads();

    int b = blockIdx.y;
    int rows[2] = { (int)blockIdx.x, (int)blockIdx.x + 512 };

    float vr[2][3];
#pragma unroll
    for (int r = 0; r < 2; ++r) {
        const float* vi = &g_vn[(b * NPTS + rows[r]) * 3];
        vr[r][0] = vi[0]; vr[r][1] = vi[1]; vr[r][2] = vi[2];
    }

    int jj[4];
    float s[4], c[4], s1[4], c1[4];
#pragma unroll
    for (int p = 0; p < 4; ++p) {
        int r = p >> 1;
        int d = 1 + tid + 256 * (p & 1);          // 1..512
        int j = (rows[r] + d) & (NPTS - 1);
        jj[p] = j;
        const float* vj = &g_vn[(b * NPTS + j) * 3];
        float dx = vr[r][0] - vj[0];
        float dy = vr[r][1] - vj[1];
        float dz = vr[r][2] - vj[2];
        float dot = 1.0f - 0.5f * ((dx * dx + dy * dy) + dz * dz);
        dot = fminf(fmaxf(dot, -1.0f), 1.0f);
        float angle = acosf(dot) * 200.0f;        // / 0.005
        float t = angle * (10.0f / 31.0f);        // base phase step

        // range-reduce t mod 2*pi in double (once per pair), then fast sin/cos
        double td = (double)t;
        double q = rint(td * 0.15915494309189535);   // 1/(2*pi)
        float tr = (float)(td - q * 6.283185307179586);
        s1[p] = __sinf(tr);
        c1[p] = __cosf(tr);
        s[p] = 0.0f;   // sin(0*t)
        c[p] = 1.0f;   // cos(0*t)
    }

    // accumulators: 4 pairs x 8 packed f32x2 = 16 heads each, init with bias
    unsigned long long acc[4][8];
    {
        unsigned long long bb[8];
#pragma unroll
        for (int q = 0; q < 8; ++q) bb[q] = pack2(sB[2 * q], sB[2 * q + 1]);
#pragma unroll
        for (int p = 0; p < 4; ++p)
#pragma unroll
            for (int q = 0; q < 8; ++q) acc[p][q] = bb[q];
    }

    const ulonglong2* sWs2 = (const ulonglong2*)sW;             // 4 u2 per row
    const ulonglong2* sWc2 = (const ulonglong2*)(sW + NF * NH);

#pragma unroll 2
    for (int k = 0; k < NF; ++k) {
        // hoist the 8 weight vectors for this frequency; reuse across 4 pairs
        ulonglong2 a0 = sWs2[4 * k + 0];
        ulonglong2 a1 = sWs2[4 * k + 1];
        ulonglong2 a2 = sWs2[4 * k + 2];
        ulonglong2 a3 = sWs2[4 * k + 3];
        ulonglong2 w0 = sWc2[4 * k + 0];
        ulonglong2 w1 = sWc2[4 * k + 1];
        ulonglong2 w2 = sWc2[4 * k + 2];
        ulonglong2 w3 = sWc2[4 * k + 3];
#pragma unroll
        for (int p = 0; p < 4; ++p) {
            unsigned long long sp = pack_dup(s[p]);
            unsigned long long cp = pack_dup(c[p]);
            fma2(acc[p][0], sp, a0.x); fma2(acc[p][1], sp, a0.y);
            fma2(acc[p][2], sp, a1.x); fma2(acc[p][3], sp, a1.y);
            fma2(acc[p][4], sp, a2.x); fma2(acc[p][5], sp, a2.y);
            fma2(acc[p][6], sp, a3.x); fma2(acc[p][7], sp, a3.y);
            fma2(acc[p][0], cp, w0.x); fma2(acc[p][1], cp, w0.y);
            fma2(acc[p][2], cp, w1.x); fma2(acc[p][3], cp, w1.y);
            fma2(acc[p][4], cp, w2.x); fma2(acc[p][5], cp, w2.y);
            fma2(acc[p][6], cp, w3.x); fma2(acc[p][7], cp, w3.y);
            // rotate: (s, c) -> (s*c1 + c*s1, c*c1 - s*s1)
            float ns = fmaf(s[p], c1[p], c[p] * s1[p]);
            float nc = fmaf(c[p], c1[p], -(s[p] * s1[p]));
            s[p] = ns;
            c[p] = nc;
        }
    }

    // each pair writes out[b,i,j,:] and out[b,j,i,:] (16 floats each)
    long long bb = (long long)b * NPTS;
#pragma unroll
    for (int p = 0; p < 4; ++p) {
        int r = p >> 1;
        int i = rows[r];
        int j = jj[p];
        float4 v[4];
#pragma unroll
        for (int q = 0; q < 4; ++q) {
            float2 lo = unpack2(acc[p][2 * q]);
            float2 hi = unpack2(acc[p][2 * q + 1]);
            v[q] = make_float4(lo.x, lo.y, hi.x, hi.y);
        }
        float4* o_ij = (float4*)out + ((bb + i) * NPTS + j) * 4;
        float4* o_ji = (float4*)out + ((bb + j) * NPTS + i) * 4;
#pragma unroll
        for (int q = 0; q < 4; ++q) o_ij[q] = v[q];
#pragma unroll
        for (int q = 0; q < 4; ++q) o_ji[q] = v[q];
    }
}

extern "C" void kernel_launch(void* const* d_in, const int* in_sizes, int n_in,
                              void* d_out, int out_size) {
    const float* vec_map = (const float*)d_in[0];
    const float* kernelW = (const float*)d_in[1];
    const float* bias    = (const float*)d_in[2];
    float* out = (float*)d_out;

    int total_vecs = in_sizes[0] / 3;       // B * N
    int B = total_vecs / NPTS;

    normalize_kernel<<<(total_vecs + 255) / 256, 256>>>(vec_map, total_vecs);
    diag_kernel<<<(total_vecs + 127) / 128, 128>>>(kernelW, bias, out, total_vecs);

    dim3 grid(NPTS / 2, B);
    relbias_kernel<<<grid, 256>>>(kernelW, bias, out);
}